// round 1
// baseline (speedup 1.0000x reference)
#include <cuda_runtime.h>
#include <cuda_bf16.h>
#include <math.h>

// ---------------------------------------------------------------------------
// ResamplerSD3: 8-layer Perceiver resampler, fp32.
// B=32, N1=257, EMB=768, DIM=1024, HEADS=16, DH=64, NQ=64, FF=4096, OUT=1024
// ---------------------------------------------------------------------------

#define Bb   32
#define N1   257
#define EMB  768
#define DIM  1024
#define HEADS 16
#define DH   64
#define NQ   64
#define FFI  4096
#define NK   (N1 + NQ)        // 321
#define DEPTH 8

// ---------------- static device scratch (no allocations allowed) -----------
__device__ float g_xf   [Bb * N1 * DIM];     // proj_in output            33.7MB
__device__ float g_cat  [Bb * NK * DIM];     // concat(ln(xf), ln(lat))   42MB
__device__ float g_lat  [Bb * NQ * DIM];     // latents state              8MB
__device__ float g_lnlat[Bb * NQ * DIM];     // ln(lat) scratch            8MB
__device__ float g_q    [Bb * NQ * DIM];     // q projection               8MB
__device__ float g_kv   [Bb * NK * 2 * DIM]; // kv projection             84MB
__device__ float g_o    [Bb * NQ * DIM];     // attention output           8MB
__device__ float g_h    [Bb * NQ * FFI];     // FF hidden                 33.6MB
__device__ float g_tmp  [Bb * NQ * DIM];     // proj_out pre-LN            8MB

// ---------------------------------------------------------------------------
// SGEMM: C[M,N] = A[M,K] @ B[K,N] (+bias) (gelu?) (+res), all row-major fp32.
// 128x128 tile, 256 threads, 8x8 per thread, BK=8, float4 global loads.
// N and K must be multiples of 128 and 8 respectively (true for all calls).
// M guarded.
// ---------------------------------------------------------------------------
__global__ __launch_bounds__(256, 1)
void sgemm_kernel(int M, int N, int K,
                  const float* __restrict__ A,
                  const float* __restrict__ B,
                  float* __restrict__ C,
                  const float* __restrict__ bias,
                  const float* __restrict__ res,
                  int do_gelu)
{
    const int BM = 128, BN = 128, BK = 8, TM = 8, TN = 8;
    __shared__ float As[BK][BM];
    __shared__ float Bs[BK][BN];

    const int bx = blockIdx.x;           // N tile
    const int by = blockIdx.y;           // M tile
    const int tid = threadIdx.x;

    const int tcol = tid % (BN / TN);    // 0..15
    const int trow = tid / (BN / TN);    // 0..15

    // A-tile load mapping: 128x8 floats = 256 float4
    const int aRow = tid / 2;            // 0..127
    const int aCol = (tid % 2) * 4;      // 0 or 4
    // B-tile load mapping: 8x128 floats = 256 float4
    const int bRow = tid / 32;           // 0..7
    const int bCol = (tid % 32) * 4;     // 0..124

    const int gARow = by * BM + aRow;
    const long gBColBase = (long)bx * BN + bCol;

    float acc[TM][TN];
#pragma unroll
    for (int i = 0; i < TM; i++)
#pragma unroll
        for (int j = 0; j < TN; j++) acc[i][j] = 0.0f;

    for (int k0 = 0; k0 < K; k0 += BK) {
        float4 av = make_float4(0.f, 0.f, 0.f, 0.f);
        if (gARow < M)
            av = *(const float4*)(A + (size_t)gARow * K + k0 + aCol);
        As[aCol + 0][aRow] = av.x;
        As[aCol + 1][aRow] = av.y;
        As[aCol + 2][aRow] = av.z;
        As[aCol + 3][aRow] = av.w;

        float4 bv = *(const float4*)(B + (size_t)(k0 + bRow) * N + gBColBase);
        *(float4*)(&Bs[bRow][bCol]) = bv;

        __syncthreads();

        float ra[TM], rb[TN];
#pragma unroll
        for (int kk = 0; kk < BK; kk++) {
#pragma unroll
            for (int i = 0; i < TM; i++) ra[i] = As[kk][trow * TM + i];
#pragma unroll
            for (int j = 0; j < TN; j++) rb[j] = Bs[kk][tcol * TN + j];
#pragma unroll
            for (int i = 0; i < TM; i++)
#pragma unroll
                for (int j = 0; j < TN; j++)
                    acc[i][j] = fmaf(ra[i], rb[j], acc[i][j]);
        }
        __syncthreads();
    }

    // epilogue
#pragma unroll
    for (int i = 0; i < TM; i++) {
        int row = by * BM + trow * TM + i;
        if (row >= M) continue;
#pragma unroll
        for (int j = 0; j < TN; j++) {
            int col = bx * BN + tcol * TN + j;
            float v = acc[i][j];
            if (bias) v += bias[col];
            if (do_gelu) v = 0.5f * v * (1.0f + erff(v * 0.70710678118654752f));
            if (res) v += res[(size_t)row * N + col];
            C[(size_t)row * N + col] = v;
        }
    }
}

// ---------------------------------------------------------------------------
// LayerNorm over width=1024. One block (256 thr) per row.
// Output row remapping: bi = row / rpb_in; n = row % rpb_in;
//   out_row = bi * rpb_out + out_off + n
// ---------------------------------------------------------------------------
__device__ __forceinline__ float2 block_reduce2(float a, float b)
{
    __shared__ float sa[8], sb[8];
#pragma unroll
    for (int off = 16; off; off >>= 1) {
        a += __shfl_down_sync(0xFFFFFFFFu, a, off);
        b += __shfl_down_sync(0xFFFFFFFFu, b, off);
    }
    int w = threadIdx.x >> 5, l = threadIdx.x & 31;
    if (l == 0) { sa[w] = a; sb[w] = b; }
    __syncthreads();
    if (w == 0) {
        a = (l < 8) ? sa[l] : 0.f;
        b = (l < 8) ? sb[l] : 0.f;
#pragma unroll
        for (int off = 4; off; off >>= 1) {
            a += __shfl_down_sync(0xFFFFFFFFu, a, off);
            b += __shfl_down_sync(0xFFFFFFFFu, b, off);
        }
        if (l == 0) { sa[0] = a; sb[0] = b; }
    }
    __syncthreads();
    return make_float2(sa[0], sb[0]);
}

__global__ __launch_bounds__(256)
void ln_kernel(const float* __restrict__ in, float* __restrict__ out,
               const float* __restrict__ g, const float* __restrict__ bta,
               int width, int rpb_in, int rpb_out, int out_off)
{
    int row = blockIdx.x;
    const float* x = in + (size_t)row * width;
    int bi = row / rpb_in, n = row % rpb_in;
    float* y = out + ((size_t)bi * rpb_out + out_off + n) * width;

    float s = 0.f, s2 = 0.f;
    for (int i = threadIdx.x * 4; i < width; i += blockDim.x * 4) {
        float4 v = *(const float4*)(x + i);
        s  += v.x + v.y + v.z + v.w;
        s2 += v.x * v.x + v.y * v.y + v.z * v.z + v.w * v.w;
    }
    float2 r = block_reduce2(s, s2);
    float mean = r.x / (float)width;
    float var  = r.y / (float)width - mean * mean;
    float rstd = rsqrtf(var + 1e-5f);

    for (int i = threadIdx.x * 4; i < width; i += blockDim.x * 4) {
        float4 v = *(const float4*)(x + i);
        float4 gg = *(const float4*)(g + i);
        float4 bb = *(const float4*)(bta + i);
        float4 o;
        o.x = (v.x - mean) * rstd * gg.x + bb.x;
        o.y = (v.y - mean) * rstd * gg.y + bb.y;
        o.z = (v.z - mean) * rstd * gg.z + bb.z;
        o.w = (v.w - mean) * rstd * gg.w + bb.w;
        *(float4*)(y + i) = o;
    }
}

// ---------------------------------------------------------------------------
// Broadcast latents (1,NQ,DIM) -> lat (B,NQ,DIM)
// ---------------------------------------------------------------------------
__global__ void bcast_kernel(const float* __restrict__ latents, float* __restrict__ lat)
{
    size_t i = (size_t)blockIdx.x * blockDim.x + threadIdx.x;
    size_t tot = (size_t)Bb * NQ * DIM;
    if (i < tot) lat[i] = latents[i % ((size_t)NQ * DIM)];
}

// ---------------------------------------------------------------------------
// Attention: per block handles (b, h, q-tile of 16 rows).
// q: (B,NQ,DIM) cols h*64+d ; kv: (B,NK,2*DIM): k cols h*64+d, v cols DIM+h*64+d
// o: (B,NQ,DIM) cols h*64+d. logits scaled by 1/8 (= (dh^-0.25)^2).
// ---------------------------------------------------------------------------
__global__ __launch_bounds__(256)
void attn_kernel(const float* __restrict__ q,
                 const float* __restrict__ kv,
                 float* __restrict__ o)
{
    __shared__ float qs[16][DH];
    __shared__ float sc[16][NK];

    int blk = blockIdx.x;
    int qt = blk & 3;              // 0..3 (16-row q tile)
    int h  = (blk >> 2) & 15;
    int b  = blk >> 6;

    const float* qbase = q + ((size_t)b * NQ + qt * 16) * DIM + h * DH;
    for (int i = threadIdx.x; i < 16 * DH; i += 256) {
        int r = i >> 6, c = i & 63;
        qs[r][c] = qbase[(size_t)r * DIM + c];
    }
    __syncthreads();

    const float* kbase = kv + (size_t)b * NK * (2 * DIM) + h * DH;
    const float* vbase = kbase + DIM;

    // scores
    for (int idx = threadIdx.x; idx < 16 * NK; idx += 256) {
        int r = idx / NK, kk = idx % NK;
        const float* krow = kbase + (size_t)kk * (2 * DIM);
        float acc = 0.f;
#pragma unroll
        for (int d = 0; d < DH; d += 4) {
            float4 k4 = *(const float4*)(krow + d);
            acc += qs[r][d] * k4.x + qs[r][d + 1] * k4.y
                 + qs[r][d + 2] * k4.z + qs[r][d + 3] * k4.w;
        }
        sc[r][kk] = acc * 0.125f;
    }
    __syncthreads();

    // softmax: warp w does rows 2w, 2w+1
    int warp = threadIdx.x >> 5, lane = threadIdx.x & 31;
    for (int r = warp * 2; r < warp * 2 + 2; r++) {
        float mx = -1e30f;
        for (int k = lane; k < NK; k += 32) mx = fmaxf(mx, sc[r][k]);
#pragma unroll
        for (int off = 16; off; off >>= 1)
            mx = fmaxf(mx, __shfl_xor_sync(0xFFFFFFFFu, mx, off));
        float sum = 0.f;
        for (int k = lane; k < NK; k += 32) {
            float e = __expf(sc[r][k] - mx);
            sc[r][k] = e;
            sum += e;
        }
#pragma unroll
        for (int off = 16; off; off >>= 1)
            sum += __shfl_xor_sync(0xFFFFFFFFu, sum, off);
        float inv = 1.0f / sum;
        for (int k = lane; k < NK; k += 32) sc[r][k] *= inv;
    }
    __syncthreads();

    // output: thread d = tid%64, base row r0 = tid/64 (rows r0, r0+4, r0+8, r0+12)
    int d = threadIdx.x & 63;
    int r0 = threadIdx.x >> 6;
    float acc[4] = {0.f, 0.f, 0.f, 0.f};
    for (int k = 0; k < NK; k++) {
        float vv = vbase[(size_t)k * (2 * DIM) + d];
#pragma unroll
        for (int j = 0; j < 4; j++)
            acc[j] = fmaf(sc[r0 + 4 * j][k], vv, acc[j]);
    }
    float* obase = o + ((size_t)b * NQ + qt * 16) * DIM + h * DH;
#pragma unroll
    for (int j = 0; j < 4; j++)
        obase[(size_t)(r0 + 4 * j) * DIM + d] = acc[j];
}

// ---------------------------------------------------------------------------
// host-side helpers
// ---------------------------------------------------------------------------
static inline void gemm(const float* A, const float* B, float* C,
                        int M, int N, int K,
                        const float* bias, const float* res, int do_gelu)
{
    dim3 grid(N / 128, (M + 127) / 128);
    sgemm_kernel<<<grid, 256>>>(M, N, K, A, B, C, bias, res, do_gelu);
}

extern "C" void kernel_launch(void* const* d_in, const int* in_sizes, int n_in,
                              void* d_out, int out_size)
{
    const float* x          = (const float*)d_in[0];
    const float* latents    = (const float*)d_in[1];
    const float* proj_in_w  = (const float*)d_in[2];
    const float* proj_in_b  = (const float*)d_in[3];
    const float* ln1_g      = (const float*)d_in[4];
    const float* ln1_b      = (const float*)d_in[5];
    const float* ln2_g      = (const float*)d_in[6];
    const float* ln2_b      = (const float*)d_in[7];
    const float* Wq         = (const float*)d_in[8];
    const float* Wkv        = (const float*)d_in[9];
    const float* Wo         = (const float*)d_in[10];
    const float* ff_ln_g    = (const float*)d_in[11];
    const float* ff_ln_b    = (const float*)d_in[12];
    const float* ff_w1      = (const float*)d_in[13];
    const float* ff_w2      = (const float*)d_in[14];
    const float* proj_out_w = (const float*)d_in[15];
    const float* proj_out_b = (const float*)d_in[16];
    const float* norm_out_g = (const float*)d_in[17];
    const float* norm_out_b = (const float*)d_in[18];
    float* out = (float*)d_out;

    float *xf, *cat, *lat, *lnlat, *qb, *kvb, *ob, *hb, *tmp;
    cudaGetSymbolAddress((void**)&xf,    g_xf);
    cudaGetSymbolAddress((void**)&cat,   g_cat);
    cudaGetSymbolAddress((void**)&lat,   g_lat);
    cudaGetSymbolAddress((void**)&lnlat, g_lnlat);
    cudaGetSymbolAddress((void**)&qb,    g_q);
    cudaGetSymbolAddress((void**)&kvb,   g_kv);
    cudaGetSymbolAddress((void**)&ob,    g_o);
    cudaGetSymbolAddress((void**)&hb,    g_h);
    cudaGetSymbolAddress((void**)&tmp,   g_tmp);

    const int Mx  = Bb * N1;   // 8224
    const int Ml  = Bb * NQ;   // 2048
    const int Mc  = Bb * NK;   // 10272

    // 1) broadcast latents
    {
        size_t tot = (size_t)Bb * NQ * DIM;
        bcast_kernel<<<(int)((tot + 255) / 256), 256>>>(latents, lat);
    }

    // 2) proj_in: xf = x @ proj_in_w + b
    gemm(x, proj_in_w, xf, Mx, DIM, EMB, proj_in_b, nullptr, 0);

    for (int i = 0; i < DEPTH; i++) {
        const float* wq  = Wq    + (size_t)i * DIM * DIM;
        const float* wkv = Wkv   + (size_t)i * DIM * 2 * DIM;
        const float* wo  = Wo    + (size_t)i * DIM * DIM;
        const float* w1  = ff_w1 + (size_t)i * DIM * FFI;
        const float* w2  = ff_w2 + (size_t)i * FFI * DIM;

        // ln(xf) -> cat rows [0,257) per batch
        ln_kernel<<<Mx, 256>>>(xf, cat, ln1_g + (size_t)i * DIM, ln1_b + (size_t)i * DIM,
                               DIM, N1, NK, 0);
        // ln(lat) -> lnlat (contig) and cat rows [257,321)
        ln_kernel<<<Ml, 256>>>(lat, lnlat, ln2_g + (size_t)i * DIM, ln2_b + (size_t)i * DIM,
                               DIM, NQ, NQ, 0);
        ln_kernel<<<Ml, 256>>>(lat, cat, ln2_g + (size_t)i * DIM, ln2_b + (size_t)i * DIM,
                               DIM, NQ, NK, N1);

        // q = lnlat @ Wq[i]
        gemm(lnlat, wq, qb, Ml, DIM, DIM, nullptr, nullptr, 0);
        // kv = cat @ Wkv[i]
        gemm(cat, wkv, kvb, Mc, 2 * DIM, DIM, nullptr, nullptr, 0);

        // attention
        attn_kernel<<<Bb * HEADS * 4, 256>>>(qb, kvb, ob);

        // lat = o @ Wo[i] + lat
        gemm(ob, wo, lat, Ml, DIM, DIM, nullptr, lat, 0);

        // FF
        ln_kernel<<<Ml, 256>>>(lat, lnlat, ff_ln_g + (size_t)i * DIM, ff_ln_b + (size_t)i * DIM,
                               DIM, NQ, NQ, 0);
        gemm(lnlat, w1, hb, Ml, FFI, DIM, nullptr, nullptr, 1);   // gelu
        gemm(hb, w2, lat, Ml, DIM, FFI, nullptr, lat, 0);         // +residual
    }

    // proj_out + final LN
    gemm(lat, proj_out_w, tmp, Ml, DIM, DIM, proj_out_b, nullptr, 0);
    ln_kernel<<<Ml, 256>>>(tmp, out, norm_out_g, norm_out_b, DIM, NQ, NQ, 0);
}

// round 2
// speedup vs baseline: 2.0346x; 2.0346x over previous
#include <cuda_runtime.h>
#include <cuda_bf16.h>
#include <math.h>
#include <stdint.h>

// ---------------------------------------------------------------------------
// ResamplerSD3: 8-layer Perceiver resampler. TF32 tensor-core GEMMs.
// B=32, N1=257, EMB=768, DIM=1024, HEADS=16, DH=64, NQ=64, FF=4096
// ---------------------------------------------------------------------------

#define Bb   32
#define N1   257
#define EMB  768
#define DIM  1024
#define HEADS 16
#define DH   64
#define NQ   64
#define FFI  4096
#define NK   (N1 + NQ)        // 321
#define DEPTH 8

// ---------------- static device scratch (no allocations allowed) -----------
__device__ float g_xf   [Bb * N1 * DIM];
__device__ float g_cat  [Bb * NK * DIM];
__device__ float g_lat  [Bb * NQ * DIM];
__device__ float g_lnlat[Bb * NQ * DIM];
__device__ float g_q    [Bb * NQ * DIM];
__device__ float g_kv   [Bb * NK * 2 * DIM];
__device__ float g_o    [Bb * NQ * DIM];
__device__ float g_h    [Bb * NQ * FFI];
__device__ float g_tmp  [Bb * NQ * DIM];

// ---------------------------------------------------------------------------
__device__ __forceinline__ uint32_t f2tf32(float x)
{
    uint32_t r;
    asm("cvt.rna.tf32.f32 %0, %1;" : "=r"(r) : "f"(x));
    return r;
}

__device__ __forceinline__ void mma_tf32(float* d, const uint32_t* a, const uint32_t* b)
{
    asm volatile(
        "mma.sync.aligned.m16n8k8.row.col.f32.tf32.tf32.f32 "
        "{%0,%1,%2,%3}, {%4,%5,%6,%7}, {%8,%9}, {%0,%1,%2,%3};\n"
        : "+f"(d[0]), "+f"(d[1]), "+f"(d[2]), "+f"(d[3])
        : "r"(a[0]), "r"(a[1]), "r"(a[2]), "r"(a[3]), "r"(b[0]), "r"(b[1]));
}

// ---------------------------------------------------------------------------
// TF32 GEMM: C[M,N] = A[M,K] @ B[K,N] (+bias) (gelu?) (+res), row-major fp32.
// CTA tile 128x128, BK=16, 256 threads (8 warps, 4x2), warp tile 32x64.
// N % 128 == 0, K % 16 == 0 required (true for all calls). M guarded.
// ---------------------------------------------------------------------------
__global__ __launch_bounds__(256)
void tgemm_kernel(int M, int N, int K,
                  const float* __restrict__ A,
                  const float* __restrict__ B,
                  float* __restrict__ C,
                  const float* __restrict__ bias,
                  const float* __restrict__ res,
                  int do_gelu)
{
    __shared__ uint32_t As[2][128][20];   // [m][k], stride 20 (bank-safe)
    __shared__ uint32_t Bs[2][16][136];   // [k][n], stride 136 (mod32 = 8, bank-safe)

    const int tid  = threadIdx.x;
    const int bx   = blockIdx.x;        // N tile
    const int by   = blockIdx.y;        // M tile
    const int wid  = tid >> 5;
    const int lane = tid & 31;
    const int gid  = lane >> 2;         // 0..7
    const int tig  = lane & 3;          // 0..3

    const int warp_m = (wid & 3) * 32;  // 4 warps along M
    const int warp_n = (wid >> 2) * 64; // 2 warps along N

    // ---- global load mappings ----
    // A tile: 128 rows x 16 cols. thread: col4=(t&3)*4, rows (t>>2)+64*i, i=0..1
    const int aCol = (tid & 3) * 4;
    const int aRow = tid >> 2;          // 0..63
    // B tile: 16 rows x 128 cols. thread: col4=(t&31)*4, rows (t>>5)+8*i
    const int bCol = (tid & 31) * 4;
    const int bRow = tid >> 5;          // 0..7

    float4 aReg[2], bReg[2];
    float acc[2][8][4];
#pragma unroll
    for (int mm = 0; mm < 2; mm++)
#pragma unroll
        for (int nn = 0; nn < 8; nn++)
#pragma unroll
            for (int r = 0; r < 4; r++) acc[mm][nn][r] = 0.0f;

    const int nk = K / 16;

    // ---- prologue: load tile 0 ----
    {
        const int k0 = 0;
#pragma unroll
        for (int i = 0; i < 2; i++) {
            int row = by * 128 + aRow + 64 * i;
            aReg[i] = (row < M) ? *(const float4*)(A + (size_t)row * K + k0 + aCol)
                                : make_float4(0.f, 0.f, 0.f, 0.f);
            bReg[i] = *(const float4*)(B + (size_t)(k0 + bRow + 8 * i) * N + bx * 128 + bCol);
        }
#pragma unroll
        for (int i = 0; i < 2; i++) {
            uint32_t* ap = &As[0][aRow + 64 * i][aCol];
            ap[0] = f2tf32(aReg[i].x); ap[1] = f2tf32(aReg[i].y);
            ap[2] = f2tf32(aReg[i].z); ap[3] = f2tf32(aReg[i].w);
            uint32_t* bp = &Bs[0][bRow + 8 * i][bCol];
            bp[0] = f2tf32(bReg[i].x); bp[1] = f2tf32(bReg[i].y);
            bp[2] = f2tf32(bReg[i].z); bp[3] = f2tf32(bReg[i].w);
        }
    }
    __syncthreads();

    for (int kt = 0; kt < nk; kt++) {
        const int buf = kt & 1;

        // issue next tile's global loads (latency hidden by compute)
        if (kt + 1 < nk) {
            const int k0 = (kt + 1) * 16;
#pragma unroll
            for (int i = 0; i < 2; i++) {
                int row = by * 128 + aRow + 64 * i;
                aReg[i] = (row < M) ? *(const float4*)(A + (size_t)row * K + k0 + aCol)
                                    : make_float4(0.f, 0.f, 0.f, 0.f);
                bReg[i] = *(const float4*)(B + (size_t)(k0 + bRow + 8 * i) * N + bx * 128 + bCol);
            }
        }

        // compute: 2 k-steps of m16n8k8
#pragma unroll
        for (int s = 0; s < 2; s++) {
            const int kb = s * 8;
            uint32_t a[2][4], b[8][2];
#pragma unroll
            for (int mm = 0; mm < 2; mm++) {
                int r0 = warp_m + mm * 16 + gid;
                a[mm][0] = As[buf][r0][kb + tig];
                a[mm][1] = As[buf][r0 + 8][kb + tig];
                a[mm][2] = As[buf][r0][kb + tig + 4];
                a[mm][3] = As[buf][r0 + 8][kb + tig + 4];
            }
#pragma unroll
            for (int nn = 0; nn < 8; nn++) {
                int c0 = warp_n + nn * 8 + gid;
                b[nn][0] = Bs[buf][kb + tig][c0];
                b[nn][1] = Bs[buf][kb + tig + 4][c0];
            }
#pragma unroll
            for (int mm = 0; mm < 2; mm++)
#pragma unroll
                for (int nn = 0; nn < 8; nn++)
                    mma_tf32(acc[mm][nn], a[mm], b[nn]);
        }

        // store next tile into other buffer
        if (kt + 1 < nk) {
            const int nbuf = buf ^ 1;
#pragma unroll
            for (int i = 0; i < 2; i++) {
                uint32_t* ap = &As[nbuf][aRow + 64 * i][aCol];
                ap[0] = f2tf32(aReg[i].x); ap[1] = f2tf32(aReg[i].y);
                ap[2] = f2tf32(aReg[i].z); ap[3] = f2tf32(aReg[i].w);
                uint32_t* bp = &Bs[nbuf][bRow + 8 * i][bCol];
                bp[0] = f2tf32(bReg[i].x); bp[1] = f2tf32(bReg[i].y);
                bp[2] = f2tf32(bReg[i].z); bp[3] = f2tf32(bReg[i].w);
            }
        }
        __syncthreads();
    }

    // ---- epilogue ----
#pragma unroll
    for (int mm = 0; mm < 2; mm++) {
#pragma unroll
        for (int half = 0; half < 2; half++) {
            int row = by * 128 + warp_m + mm * 16 + gid + half * 8;
            if (row >= M) continue;
#pragma unroll
            for (int nn = 0; nn < 8; nn++) {
                int col = bx * 128 + warp_n + nn * 8 + tig * 2;
                float v0 = acc[mm][nn][half * 2 + 0];
                float v1 = acc[mm][nn][half * 2 + 1];
                if (bias) { v0 += bias[col]; v1 += bias[col + 1]; }
                if (do_gelu) {
                    v0 = 0.5f * v0 * (1.0f + erff(v0 * 0.70710678118654752f));
                    v1 = 0.5f * v1 * (1.0f + erff(v1 * 0.70710678118654752f));
                }
                if (res) {
                    v0 += res[(size_t)row * N + col];
                    v1 += res[(size_t)row * N + col + 1];
                }
                C[(size_t)row * N + col]     = v0;
                C[(size_t)row * N + col + 1] = v1;
            }
        }
    }
}

// ---------------------------------------------------------------------------
// LayerNorm over width=1024. One block (256 thr) per row.
// ---------------------------------------------------------------------------
__device__ __forceinline__ float2 block_reduce2(float a, float b)
{
    __shared__ float sa[8], sb[8];
#pragma unroll
    for (int off = 16; off; off >>= 1) {
        a += __shfl_down_sync(0xFFFFFFFFu, a, off);
        b += __shfl_down_sync(0xFFFFFFFFu, b, off);
    }
    int w = threadIdx.x >> 5, l = threadIdx.x & 31;
    if (l == 0) { sa[w] = a; sb[w] = b; }
    __syncthreads();
    if (w == 0) {
        a = (l < 8) ? sa[l] : 0.f;
        b = (l < 8) ? sb[l] : 0.f;
#pragma unroll
        for (int off = 4; off; off >>= 1) {
            a += __shfl_down_sync(0xFFFFFFFFu, a, off);
            b += __shfl_down_sync(0xFFFFFFFFu, b, off);
        }
        if (l == 0) { sa[0] = a; sb[0] = b; }
    }
    __syncthreads();
    return make_float2(sa[0], sb[0]);
}

__global__ __launch_bounds__(256)
void ln_kernel(const float* __restrict__ in, float* __restrict__ out,
               const float* __restrict__ g, const float* __restrict__ bta,
               int width, int rpb_in, int rpb_out, int out_off)
{
    int row = blockIdx.x;
    const float* x = in + (size_t)row * width;
    int bi = row / rpb_in, n = row % rpb_in;
    float* y = out + ((size_t)bi * rpb_out + out_off + n) * width;

    float s = 0.f, s2 = 0.f;
    for (int i = threadIdx.x * 4; i < width; i += blockDim.x * 4) {
        float4 v = *(const float4*)(x + i);
        s  += v.x + v.y + v.z + v.w;
        s2 += v.x * v.x + v.y * v.y + v.z * v.z + v.w * v.w;
    }
    float2 r = block_reduce2(s, s2);
    float mean = r.x / (float)width;
    float var  = r.y / (float)width - mean * mean;
    float rstd = rsqrtf(var + 1e-5f);

    for (int i = threadIdx.x * 4; i < width; i += blockDim.x * 4) {
        float4 v = *(const float4*)(x + i);
        float4 gg = *(const float4*)(g + i);
        float4 bb = *(const float4*)(bta + i);
        float4 o;
        o.x = (v.x - mean) * rstd * gg.x + bb.x;
        o.y = (v.y - mean) * rstd * gg.y + bb.y;
        o.z = (v.z - mean) * rstd * gg.z + bb.z;
        o.w = (v.w - mean) * rstd * gg.w + bb.w;
        *(float4*)(y + i) = o;
    }
}

__global__ void bcast_kernel(const float* __restrict__ latents, float* __restrict__ lat)
{
    size_t i = (size_t)blockIdx.x * blockDim.x + threadIdx.x;
    size_t tot = (size_t)Bb * NQ * DIM;
    if (i < tot) lat[i] = latents[i % ((size_t)NQ * DIM)];
}

// ---------------------------------------------------------------------------
// Attention: per block handles (b, h, q-tile of 16 rows). fp32.
// ---------------------------------------------------------------------------
__global__ __launch_bounds__(256)
void attn_kernel(const float* __restrict__ q,
                 const float* __restrict__ kv,
                 float* __restrict__ o)
{
    __shared__ float qs[16][DH];
    __shared__ float sc[16][NK];

    int blk = blockIdx.x;
    int qt = blk & 3;
    int h  = (blk >> 2) & 15;
    int b  = blk >> 6;

    const float* qbase = q + ((size_t)b * NQ + qt * 16) * DIM + h * DH;
    for (int i = threadIdx.x; i < 16 * DH; i += 256) {
        int r = i >> 6, c = i & 63;
        qs[r][c] = qbase[(size_t)r * DIM + c];
    }
    __syncthreads();

    const float* kbase = kv + (size_t)b * NK * (2 * DIM) + h * DH;
    const float* vbase = kbase + DIM;

    for (int idx = threadIdx.x; idx < 16 * NK; idx += 256) {
        int r = idx / NK, kk = idx % NK;
        const float* krow = kbase + (size_t)kk * (2 * DIM);
        float acc = 0.f;
#pragma unroll
        for (int d = 0; d < DH; d += 4) {
            float4 k4 = *(const float4*)(krow + d);
            acc += qs[r][d] * k4.x + qs[r][d + 1] * k4.y
                 + qs[r][d + 2] * k4.z + qs[r][d + 3] * k4.w;
        }
        sc[r][kk] = acc * 0.125f;
    }
    __syncthreads();

    int warp = threadIdx.x >> 5, lane = threadIdx.x & 31;
    for (int r = warp * 2; r < warp * 2 + 2; r++) {
        float mx = -1e30f;
        for (int k = lane; k < NK; k += 32) mx = fmaxf(mx, sc[r][k]);
#pragma unroll
        for (int off = 16; off; off >>= 1)
            mx = fmaxf(mx, __shfl_xor_sync(0xFFFFFFFFu, mx, off));
        float sum = 0.f;
        for (int k = lane; k < NK; k += 32) {
            float e = __expf(sc[r][k] - mx);
            sc[r][k] = e;
            sum += e;
        }
#pragma unroll
        for (int off = 16; off; off >>= 1)
            sum += __shfl_xor_sync(0xFFFFFFFFu, sum, off);
        float inv = 1.0f / sum;
        for (int k = lane; k < NK; k += 32) sc[r][k] *= inv;
    }
    __syncthreads();

    int d = threadIdx.x & 63;
    int r0 = threadIdx.x >> 6;
    float acc[4] = {0.f, 0.f, 0.f, 0.f};
    for (int k = 0; k < NK; k++) {
        float vv = vbase[(size_t)k * (2 * DIM) + d];
#pragma unroll
        for (int j = 0; j < 4; j++)
            acc[j] = fmaf(sc[r0 + 4 * j][k], vv, acc[j]);
    }
    float* obase = o + ((size_t)b * NQ + qt * 16) * DIM + h * DH;
#pragma unroll
    for (int j = 0; j < 4; j++)
        obase[(size_t)(r0 + 4 * j) * DIM + d] = acc[j];
}

// ---------------------------------------------------------------------------
static inline void gemm(const float* A, const float* B, float* C,
                        int M, int N, int K,
                        const float* bias, const float* res, int do_gelu)
{
    dim3 grid(N / 128, (M + 127) / 128);
    tgemm_kernel<<<grid, 256>>>(M, N, K, A, B, C, bias, res, do_gelu);
}

extern "C" void kernel_launch(void* const* d_in, const int* in_sizes, int n_in,
                              void* d_out, int out_size)
{
    const float* x          = (const float*)d_in[0];
    const float* latents    = (const float*)d_in[1];
    const float* proj_in_w  = (const float*)d_in[2];
    const float* proj_in_b  = (const float*)d_in[3];
    const float* ln1_g      = (const float*)d_in[4];
    const float* ln1_b      = (const float*)d_in[5];
    const float* ln2_g      = (const float*)d_in[6];
    const float* ln2_b      = (const float*)d_in[7];
    const float* Wq         = (const float*)d_in[8];
    const float* Wkv        = (const float*)d_in[9];
    const float* Wo         = (const float*)d_in[10];
    const float* ff_ln_g    = (const float*)d_in[11];
    const float* ff_ln_b    = (const float*)d_in[12];
    const float* ff_w1      = (const float*)d_in[13];
    const float* ff_w2      = (const float*)d_in[14];
    const float* proj_out_w = (const float*)d_in[15];
    const float* proj_out_b = (const float*)d_in[16];
    const float* norm_out_g = (const float*)d_in[17];
    const float* norm_out_b = (const float*)d_in[18];
    float* out = (float*)d_out;

    float *xf, *cat, *lat, *lnlat, *qb, *kvb, *ob, *hb, *tmp;
    cudaGetSymbolAddress((void**)&xf,    g_xf);
    cudaGetSymbolAddress((void**)&cat,   g_cat);
    cudaGetSymbolAddress((void**)&lat,   g_lat);
    cudaGetSymbolAddress((void**)&lnlat, g_lnlat);
    cudaGetSymbolAddress((void**)&qb,    g_q);
    cudaGetSymbolAddress((void**)&kvb,   g_kv);
    cudaGetSymbolAddress((void**)&ob,    g_o);
    cudaGetSymbolAddress((void**)&hb,    g_h);
    cudaGetSymbolAddress((void**)&tmp,   g_tmp);

    const int Mx  = Bb * N1;   // 8224
    const int Ml  = Bb * NQ;   // 2048
    const int Mc  = Bb * NK;   // 10272

    {
        size_t tot = (size_t)Bb * NQ * DIM;
        bcast_kernel<<<(int)((tot + 255) / 256), 256>>>(latents, lat);
    }

    gemm(x, proj_in_w, xf, Mx, DIM, EMB, proj_in_b, nullptr, 0);

    for (int i = 0; i < DEPTH; i++) {
        const float* wq  = Wq    + (size_t)i * DIM * DIM;
        const float* wkv = Wkv   + (size_t)i * DIM * 2 * DIM;
        const float* wo  = Wo    + (size_t)i * DIM * DIM;
        const float* w1  = ff_w1 + (size_t)i * DIM * FFI;
        const float* w2  = ff_w2 + (size_t)i * FFI * DIM;

        ln_kernel<<<Mx, 256>>>(xf, cat, ln1_g + (size_t)i * DIM, ln1_b + (size_t)i * DIM,
                               DIM, N1, NK, 0);
        ln_kernel<<<Ml, 256>>>(lat, lnlat, ln2_g + (size_t)i * DIM, ln2_b + (size_t)i * DIM,
                               DIM, NQ, NQ, 0);
        ln_kernel<<<Ml, 256>>>(lat, cat, ln2_g + (size_t)i * DIM, ln2_b + (size_t)i * DIM,
                               DIM, NQ, NK, N1);

        gemm(lnlat, wq, qb, Ml, DIM, DIM, nullptr, nullptr, 0);
        gemm(cat, wkv, kvb, Mc, 2 * DIM, DIM, nullptr, nullptr, 0);

        attn_kernel<<<Bb * HEADS * 4, 256>>>(qb, kvb, ob);

        gemm(ob, wo, lat, Ml, DIM, DIM, nullptr, lat, 0);

        ln_kernel<<<Ml, 256>>>(lat, lnlat, ff_ln_g + (size_t)i * DIM, ff_ln_b + (size_t)i * DIM,
                               DIM, NQ, NQ, 0);
        gemm(lnlat, w1, hb, Ml, FFI, DIM, nullptr, nullptr, 1);
        gemm(hb, w2, lat, Ml, DIM, FFI, nullptr, lat, 0);
    }

    gemm(lat, proj_out_w, tmp, Ml, DIM, DIM, proj_out_b, nullptr, 0);
    ln_kernel<<<Ml, 256>>>(tmp, out, norm_out_g, norm_out_b, DIM, NQ, NQ, 0);
}

// round 3
// speedup vs baseline: 2.1266x; 1.0452x over previous
#include <cuda_runtime.h>
#include <cuda_bf16.h>
#include <math.h>
#include <stdint.h>

// ---------------------------------------------------------------------------
// ResamplerSD3: 8-layer Perceiver resampler. TF32 tensor-core GEMMs with
// cp.async 3-stage pipeline.
// B=32, N1=257, EMB=768, DIM=1024, HEADS=16, DH=64, NQ=64, FF=4096
// ---------------------------------------------------------------------------

#define Bb   32
#define N1   257
#define EMB  768
#define DIM  1024
#define HEADS 16
#define DH   64
#define NQ   64
#define FFI  4096
#define NK   (N1 + NQ)        // 321
#define DEPTH 8

// GEMM tiling
#define GSTAGES 3
#define GBK     16
#define A_LDS   20            // A smem row stride (floats), bank-safe
#define B_LDS   136           // B smem row stride (floats), bank-safe
#define A_ST    (128 * A_LDS) // floats per A stage
#define B_ST    (GBK * B_LDS) // floats per B stage
#define GSMEM_BYTES ((GSTAGES * (A_ST + B_ST)) * 4)

// ---------------- static device scratch (no allocations allowed) -----------
__device__ float g_xf   [Bb * N1 * DIM];
__device__ float g_cat  [Bb * NK * DIM];
__device__ float g_lat  [Bb * NQ * DIM];
__device__ float g_lnlat[Bb * NQ * DIM];
__device__ float g_q    [Bb * NQ * DIM];
__device__ float g_kv   [Bb * NK * 2 * DIM];
__device__ float g_o    [Bb * NQ * DIM];
__device__ float g_h    [Bb * NQ * FFI];
__device__ float g_tmp  [Bb * NQ * DIM];

// ---------------------------------------------------------------------------
__device__ __forceinline__ uint32_t f2tf32(float x)
{
    uint32_t r;
    asm("cvt.rna.tf32.f32 %0, %1;" : "=r"(r) : "f"(x));
    return r;
}

__device__ __forceinline__ void mma_tf32(float* d, const uint32_t* a, const uint32_t* b)
{
    asm volatile(
        "mma.sync.aligned.m16n8k8.row.col.f32.tf32.tf32.f32 "
        "{%0,%1,%2,%3}, {%4,%5,%6,%7}, {%8,%9}, {%0,%1,%2,%3};\n"
        : "+f"(d[0]), "+f"(d[1]), "+f"(d[2]), "+f"(d[3])
        : "r"(a[0]), "r"(a[1]), "r"(a[2]), "r"(a[3]), "r"(b[0]), "r"(b[1]));
}

__device__ __forceinline__ void cp_async8(uint32_t dst, const float* src, bool pred)
{
    int sz = pred ? 8 : 0;
    asm volatile("cp.async.ca.shared.global [%0], [%1], 8, %2;\n"
                 :: "r"(dst), "l"(src), "r"(sz));
}
__device__ __forceinline__ void cp_async16(uint32_t dst, const float* src)
{
    asm volatile("cp.async.cg.shared.global [%0], [%1], 16;\n"
                 :: "r"(dst), "l"(src));
}
__device__ __forceinline__ void cp_commit()
{
    asm volatile("cp.async.commit_group;\n");
}

// ---------------------------------------------------------------------------
// TF32 GEMM: C[M,N] = A[M,K] @ B[K,N] (+bias) (gelu?) (+res), row-major fp32.
// CTA tile 128x128, BK=16, 3-stage cp.async pipeline, 256 threads (8 warps,
// 4x2), warp tile 32x64. N % 128 == 0, K % 16 == 0 required. M guarded.
// ---------------------------------------------------------------------------
__global__ __launch_bounds__(256)
void tgemm_kernel(int M, int N, int K,
                  const float* __restrict__ A,
                  const float* __restrict__ B,
                  float* __restrict__ C,
                  const float* __restrict__ bias,
                  const float* __restrict__ res,
                  int do_gelu)
{
    extern __shared__ float smem[];
    float* Asf = smem;                     // [GSTAGES][128][A_LDS]
    float* Bsf = smem + GSTAGES * A_ST;    // [GSTAGES][GBK][B_LDS]

    const uint32_t sA = (uint32_t)__cvta_generic_to_shared(Asf);
    const uint32_t sB = (uint32_t)__cvta_generic_to_shared(Bsf);

    const int tid  = threadIdx.x;
    const int bx   = blockIdx.x;        // N tile
    const int by   = blockIdx.y;        // M tile
    const int wid  = tid >> 5;
    const int lane = tid & 31;
    const int gid  = lane >> 2;         // 0..7
    const int tig  = lane & 3;          // 0..3

    const int warp_m = (wid & 3) * 32;  // 4 warps along M
    const int warp_n = (wid >> 2) * 64; // 2 warps along N

    // global load mappings
    const int aCol = (tid & 3) * 4;     // 0,4,8,12
    const int aRow = tid >> 2;          // 0..63  (rows aRow, aRow+64)
    const int bCol = (tid & 31) * 4;    // 0..124
    const int bRow = tid >> 5;          // 0..7   (rows bRow, bRow+8)

    const int gARow0 = by * 128 + aRow;
    const int gARow1 = gARow0 + 64;
    const float* gA0 = A + (size_t)(gARow0 < M ? gARow0 : 0) * K + aCol;
    const float* gA1 = A + (size_t)(gARow1 < M ? gARow1 : 0) * K + aCol;
    const bool pA0 = (gARow0 < M);
    const bool pA1 = (gARow1 < M);
    const float* gB0 = B + (size_t)bRow * N + bx * 128 + bCol;
    const float* gB1 = B + (size_t)(bRow + 8) * N + bx * 128 + bCol;

    const int nk = K / GBK;

    float acc[2][8][4];
#pragma unroll
    for (int mm = 0; mm < 2; mm++)
#pragma unroll
        for (int nn = 0; nn < 8; nn++)
#pragma unroll
            for (int r = 0; r < 4; r++) acc[mm][nn][r] = 0.0f;

    // issue stage copy for k-tile kt into slot
    auto issue = [&](int slot, int kt) {
        const int k0 = kt * GBK;
        uint32_t ad0 = sA + (uint32_t)((slot * A_ST) + aRow * A_LDS + aCol) * 4u;
        uint32_t ad1 = sA + (uint32_t)((slot * A_ST) + (aRow + 64) * A_LDS + aCol) * 4u;
        cp_async8(ad0,     gA0 + k0,     pA0);
        cp_async8(ad0 + 8, gA0 + k0 + 2, pA0);
        cp_async8(ad1,     gA1 + k0,     pA1);
        cp_async8(ad1 + 8, gA1 + k0 + 2, pA1);
        uint32_t bd0 = sB + (uint32_t)((slot * B_ST) + bRow * B_LDS + bCol) * 4u;
        uint32_t bd1 = sB + (uint32_t)((slot * B_ST) + (bRow + 8) * B_LDS + bCol) * 4u;
        cp_async16(bd0, gB0 + (size_t)k0 * N);
        cp_async16(bd1, gB1 + (size_t)k0 * N);
    };

    // prologue: stages 0..GSTAGES-2
#pragma unroll
    for (int s = 0; s < GSTAGES - 1; s++) {
        issue(s, s);
        cp_commit();
    }

    for (int kt = 0; kt < nk; kt++) {
        asm volatile("cp.async.wait_group %0;\n" :: "n"(GSTAGES - 2));
        __syncthreads();

        const int slot = kt % GSTAGES;
        const int nxt  = kt + GSTAGES - 1;
        if (nxt < nk) issue(nxt % GSTAGES, nxt);
        cp_commit();

        const float* As_ = Asf + slot * A_ST;
        const float* Bs_ = Bsf + slot * B_ST;

#pragma unroll
        for (int s = 0; s < 2; s++) {
            const int kb = s * 8;
            uint32_t a[2][4], b[8][2];
#pragma unroll
            for (int mm = 0; mm < 2; mm++) {
                int r0 = warp_m + mm * 16 + gid;
                a[mm][0] = f2tf32(As_[r0 * A_LDS + kb + tig]);
                a[mm][1] = f2tf32(As_[(r0 + 8) * A_LDS + kb + tig]);
                a[mm][2] = f2tf32(As_[r0 * A_LDS + kb + tig + 4]);
                a[mm][3] = f2tf32(As_[(r0 + 8) * A_LDS + kb + tig + 4]);
            }
#pragma unroll
            for (int nn = 0; nn < 8; nn++) {
                int c0 = warp_n + nn * 8 + gid;
                b[nn][0] = f2tf32(Bs_[(kb + tig) * B_LDS + c0]);
                b[nn][1] = f2tf32(Bs_[(kb + tig + 4) * B_LDS + c0]);
            }
#pragma unroll
            for (int mm = 0; mm < 2; mm++)
#pragma unroll
                for (int nn = 0; nn < 8; nn++)
                    mma_tf32(acc[mm][nn], a[mm], b[nn]);
        }
    }

    // ---- epilogue ----
#pragma unroll
    for (int mm = 0; mm < 2; mm++) {
#pragma unroll
        for (int half = 0; half < 2; half++) {
            int row = by * 128 + warp_m + mm * 16 + gid + half * 8;
            if (row >= M) continue;
#pragma unroll
            for (int nn = 0; nn < 8; nn++) {
                int col = bx * 128 + warp_n + nn * 8 + tig * 2;
                float v0 = acc[mm][nn][half * 2 + 0];
                float v1 = acc[mm][nn][half * 2 + 1];
                if (bias) { v0 += bias[col]; v1 += bias[col + 1]; }
                if (do_gelu) {
                    v0 = 0.5f * v0 * (1.0f + erff(v0 * 0.70710678118654752f));
                    v1 = 0.5f * v1 * (1.0f + erff(v1 * 0.70710678118654752f));
                }
                if (res) {
                    v0 += res[(size_t)row * N + col];
                    v1 += res[(size_t)row * N + col + 1];
                }
                C[(size_t)row * N + col]     = v0;
                C[(size_t)row * N + col + 1] = v1;
            }
        }
    }
}

// ---------------------------------------------------------------------------
// LayerNorm over width=1024, optional dual output.
// ---------------------------------------------------------------------------
__device__ __forceinline__ float2 block_reduce2(float a, float b)
{
    __shared__ float sa[8], sb[8];
#pragma unroll
    for (int off = 16; off; off >>= 1) {
        a += __shfl_down_sync(0xFFFFFFFFu, a, off);
        b += __shfl_down_sync(0xFFFFFFFFu, b, off);
    }
    int w = threadIdx.x >> 5, l = threadIdx.x & 31;
    if (l == 0) { sa[w] = a; sb[w] = b; }
    __syncthreads();
    if (w == 0) {
        a = (l < 8) ? sa[l] : 0.f;
        b = (l < 8) ? sb[l] : 0.f;
#pragma unroll
        for (int off = 4; off; off >>= 1) {
            a += __shfl_down_sync(0xFFFFFFFFu, a, off);
            b += __shfl_down_sync(0xFFFFFFFFu, b, off);
        }
        if (l == 0) { sa[0] = a; sb[0] = b; }
    }
    __syncthreads();
    return make_float2(sa[0], sb[0]);
}

__global__ __launch_bounds__(256)
void ln_kernel(const float* __restrict__ in, float* __restrict__ out,
               float* __restrict__ out2,
               const float* __restrict__ g, const float* __restrict__ bta,
               int width, int rpb_in, int rpb_out, int out_off)
{
    int row = blockIdx.x;
    const float* x = in + (size_t)row * width;
    int bi = row / rpb_in, n = row % rpb_in;
    float* y = out + ((size_t)bi * rpb_out + out_off + n) * width;
    float* y2 = out2 ? out2 + (size_t)row * width : nullptr;

    float s = 0.f, s2 = 0.f;
    for (int i = threadIdx.x * 4; i < width; i += blockDim.x * 4) {
        float4 v = *(const float4*)(x + i);
        s  += v.x + v.y + v.z + v.w;
        s2 += v.x * v.x + v.y * v.y + v.z * v.z + v.w * v.w;
    }
    float2 r = block_reduce2(s, s2);
    float mean = r.x / (float)width;
    float var  = r.y / (float)width - mean * mean;
    float rstd = rsqrtf(var + 1e-5f);

    for (int i = threadIdx.x * 4; i < width; i += blockDim.x * 4) {
        float4 v = *(const float4*)(x + i);
        float4 gg = *(const float4*)(g + i);
        float4 bb = *(const float4*)(bta + i);
        float4 o;
        o.x = (v.x - mean) * rstd * gg.x + bb.x;
        o.y = (v.y - mean) * rstd * gg.y + bb.y;
        o.z = (v.z - mean) * rstd * gg.z + bb.z;
        o.w = (v.w - mean) * rstd * gg.w + bb.w;
        *(float4*)(y + i) = o;
        if (y2) *(float4*)(y2 + i) = o;
    }
}

__global__ void bcast_kernel(const float* __restrict__ latents, float* __restrict__ lat)
{
    size_t i = (size_t)blockIdx.x * blockDim.x + threadIdx.x;
    size_t tot = (size_t)Bb * NQ * DIM;
    if (i < tot) lat[i] = latents[i % ((size_t)NQ * DIM)];
}

// ---------------------------------------------------------------------------
// Attention: per block handles (b, h, q-tile of 16 rows). fp32.
// ---------------------------------------------------------------------------
__global__ __launch_bounds__(256)
void attn_kernel(const float* __restrict__ q,
                 const float* __restrict__ kv,
                 float* __restrict__ o)
{
    __shared__ float qs[16][DH];
    __shared__ float sc[16][NK];

    int blk = blockIdx.x;
    int qt = blk & 3;
    int h  = (blk >> 2) & 15;
    int b  = blk >> 6;

    const float* qbase = q + ((size_t)b * NQ + qt * 16) * DIM + h * DH;
    for (int i = threadIdx.x; i < 16 * DH; i += 256) {
        int r = i >> 6, c = i & 63;
        qs[r][c] = qbase[(size_t)r * DIM + c];
    }
    __syncthreads();

    const float* kbase = kv + (size_t)b * NK * (2 * DIM) + h * DH;
    const float* vbase = kbase + DIM;

    for (int idx = threadIdx.x; idx < 16 * NK; idx += 256) {
        int r = idx / NK, kk = idx % NK;
        const float* krow = kbase + (size_t)kk * (2 * DIM);
        float acc = 0.f;
#pragma unroll
        for (int d = 0; d < DH; d += 4) {
            float4 k4 = *(const float4*)(krow + d);
            acc += qs[r][d] * k4.x + qs[r][d + 1] * k4.y
                 + qs[r][d + 2] * k4.z + qs[r][d + 3] * k4.w;
        }
        sc[r][kk] = acc * 0.125f;
    }
    __syncthreads();

    int warp = threadIdx.x >> 5, lane = threadIdx.x & 31;
    for (int r = warp * 2; r < warp * 2 + 2; r++) {
        float mx = -1e30f;
        for (int k = lane; k < NK; k += 32) mx = fmaxf(mx, sc[r][k]);
#pragma unroll
        for (int off = 16; off; off >>= 1)
            mx = fmaxf(mx, __shfl_xor_sync(0xFFFFFFFFu, mx, off));
        float sum = 0.f;
        for (int k = lane; k < NK; k += 32) {
            float e = __expf(sc[r][k] - mx);
            sc[r][k] = e;
            sum += e;
        }
#pragma unroll
        for (int off = 16; off; off >>= 1)
            sum += __shfl_xor_sync(0xFFFFFFFFu, sum, off);
        float inv = 1.0f / sum;
        for (int k = lane; k < NK; k += 32) sc[r][k] *= inv;
    }
    __syncthreads();

    int d = threadIdx.x & 63;
    int r0 = threadIdx.x >> 6;
    float acc[4] = {0.f, 0.f, 0.f, 0.f};
    for (int k = 0; k < NK; k++) {
        float vv = vbase[(size_t)k * (2 * DIM) + d];
#pragma unroll
        for (int j = 0; j < 4; j++)
            acc[j] = fmaf(sc[r0 + 4 * j][k], vv, acc[j]);
    }
    float* obase = o + ((size_t)b * NQ + qt * 16) * DIM + h * DH;
#pragma unroll
    for (int j = 0; j < 4; j++)
        obase[(size_t)(r0 + 4 * j) * DIM + d] = acc[j];
}

// ---------------------------------------------------------------------------
static inline void gemm(const float* A, const float* B, float* C,
                        int M, int N, int K,
                        const float* bias, const float* res, int do_gelu)
{
    dim3 grid(N / 128, (M + 127) / 128);
    tgemm_kernel<<<grid, 256, GSMEM_BYTES>>>(M, N, K, A, B, C, bias, res, do_gelu);
}

extern "C" void kernel_launch(void* const* d_in, const int* in_sizes, int n_in,
                              void* d_out, int out_size)
{
    const float* x          = (const float*)d_in[0];
    const float* latents    = (const float*)d_in[1];
    const float* proj_in_w  = (const float*)d_in[2];
    const float* proj_in_b  = (const float*)d_in[3];
    const float* ln1_g      = (const float*)d_in[4];
    const float* ln1_b      = (const float*)d_in[5];
    const float* ln2_g      = (const float*)d_in[6];
    const float* ln2_b      = (const float*)d_in[7];
    const float* Wq         = (const float*)d_in[8];
    const float* Wkv        = (const float*)d_in[9];
    const float* Wo         = (const float*)d_in[10];
    const float* ff_ln_g    = (const float*)d_in[11];
    const float* ff_ln_b    = (const float*)d_in[12];
    const float* ff_w1      = (const float*)d_in[13];
    const float* ff_w2      = (const float*)d_in[14];
    const float* proj_out_w = (const float*)d_in[15];
    const float* proj_out_b = (const float*)d_in[16];
    const float* norm_out_g = (const float*)d_in[17];
    const float* norm_out_b = (const float*)d_in[18];
    float* out = (float*)d_out;

    static bool attr_done = false;
    cudaFuncSetAttribute(tgemm_kernel,
                         cudaFuncAttributeMaxDynamicSharedMemorySize, GSMEM_BYTES);
    (void)attr_done;

    float *xf, *cat, *lat, *lnlat, *qb, *kvb, *ob, *hb, *tmp;
    cudaGetSymbolAddress((void**)&xf,    g_xf);
    cudaGetSymbolAddress((void**)&cat,   g_cat);
    cudaGetSymbolAddress((void**)&lat,   g_lat);
    cudaGetSymbolAddress((void**)&lnlat, g_lnlat);
    cudaGetSymbolAddress((void**)&qb,    g_q);
    cudaGetSymbolAddress((void**)&kvb,   g_kv);
    cudaGetSymbolAddress((void**)&ob,    g_o);
    cudaGetSymbolAddress((void**)&hb,    g_h);
    cudaGetSymbolAddress((void**)&tmp,   g_tmp);

    const int Mx  = Bb * N1;   // 8224
    const int Ml  = Bb * NQ;   // 2048
    const int Mc  = Bb * NK;   // 10272

    {
        size_t tot = (size_t)Bb * NQ * DIM;
        bcast_kernel<<<(int)((tot + 255) / 256), 256>>>(latents, lat);
    }

    gemm(x, proj_in_w, xf, Mx, DIM, EMB, proj_in_b, nullptr, 0);

    for (int i = 0; i < DEPTH; i++) {
        const float* wq  = Wq    + (size_t)i * DIM * DIM;
        const float* wkv = Wkv   + (size_t)i * DIM * 2 * DIM;
        const float* wo  = Wo    + (size_t)i * DIM * DIM;
        const float* w1  = ff_w1 + (size_t)i * DIM * FFI;
        const float* w2  = ff_w2 + (size_t)i * FFI * DIM;

        // ln(xf) -> cat rows [0,257)
        ln_kernel<<<Mx, 256>>>(xf, cat, nullptr,
                               ln1_g + (size_t)i * DIM, ln1_b + (size_t)i * DIM,
                               DIM, N1, NK, 0);
        // ln(lat) -> cat rows [257,321) AND lnlat (one pass)
        ln_kernel<<<Ml, 256>>>(lat, cat, lnlat,
                               ln2_g + (size_t)i * DIM, ln2_b + (size_t)i * DIM,
                               DIM, NQ, NK, N1);

        gemm(lnlat, wq, qb, Ml, DIM, DIM, nullptr, nullptr, 0);
        gemm(cat, wkv, kvb, Mc, 2 * DIM, DIM, nullptr, nullptr, 0);

        attn_kernel<<<Bb * HEADS * 4, 256>>>(qb, kvb, ob);

        gemm(ob, wo, lat, Ml, DIM, DIM, nullptr, lat, 0);

        ln_kernel<<<Ml, 256>>>(lat, lnlat, nullptr,
                               ff_ln_g + (size_t)i * DIM, ff_ln_b + (size_t)i * DIM,
                               DIM, NQ, NQ, 0);
        gemm(lnlat, w1, hb, Ml, FFI, DIM, nullptr, nullptr, 1);
        gemm(hb, w2, lat, Ml, DIM, FFI, nullptr, lat, 0);
    }

    gemm(lat, proj_out_w, tmp, Ml, DIM, DIM, proj_out_b, nullptr, 0);
    ln_kernel<<<Ml, 256>>>(tmp, out, nullptr, norm_out_g, norm_out_b, DIM, NQ, NQ, 0);
}

// round 5
// speedup vs baseline: 2.1392x; 1.0059x over previous
#include <cuda_runtime.h>
#include <math.h>
#include <stdint.h>

// ---------------------------------------------------------------------------
// ResamplerSD3: 8-layer Perceiver resampler.
// mma.sync tf32 GEMMs, cp.async.bulk (TMA path) smem fills, mbarrier pipeline.
// B=32, N1=257, EMB=768, DIM=1024, HEADS=16, DH=64, NQ=64, FF=4096
// ---------------------------------------------------------------------------

#define Bb   32
#define N1   257
#define EMB  768
#define DIM  1024
#define HEADS 16
#define DH   64
#define NQ   64
#define FFI  4096
#define NK   (N1 + NQ)        // 321
#define DEPTH 8

// ---- GEMM tiling: CTA 128(M) x 256(N), BK=32, 3 stages, 512 threads -------
#define STG      3
#define BKT      32
#define A_STRIDE 40                    // floats per A smem row (bank-safe)
#define B_STRIDE 264                   // floats per B smem row (bank-safe)
#define A_SB     (128 * A_STRIDE * 4)  // 20480 B
#define B_SB     (BKT * B_STRIDE * 4)  // 33792 B
#define STAGE_B  (A_SB + B_SB)         // 54272 B
#define CTRL     64
#define GSMEM    (CTRL + STG * STAGE_B)          // 162880 B
#define KT_BYTES (128 * 128 + BKT * 1024)        // 49152 B delivered per kt

// ---------------- static device scratch (no allocations allowed) -----------
__device__ float g_xf   [Bb * N1 * DIM];
__device__ float g_cat  [Bb * NK * DIM];
__device__ float g_lat  [Bb * NQ * DIM];
__device__ float g_lnlat[Bb * NQ * DIM];
__device__ float g_q    [Bb * NQ * DIM];
__device__ float g_kv   [Bb * NK * 2 * DIM];
__device__ float g_o    [Bb * NQ * DIM];
__device__ float g_h    [Bb * NQ * FFI];
__device__ float g_tmp  [Bb * NQ * DIM];
__device__ float g_xr   [Bb * N1 * EMB];      // rounded x
__device__ float g_wt   [102498304];          // all RNA-rounded weights

// offsets into g_wt (floats), original [K,N] layouts
#define OFF_PIN  0
#define OFF_WQ   (OFF_PIN + 768 * 1024)
#define OFF_WKV  (OFF_WQ  + 8 * 1024 * 1024)
#define OFF_WO   (OFF_WKV + 8 * 1024 * 2048)
#define OFF_W1   (OFF_WO  + 8 * 1024 * 1024)
#define OFF_W2   (OFF_W1  + 8 * 1024 * 4096)
#define OFF_POUT (OFF_W2  + 8 * 4096 * 1024)

// ---------------------------------------------------------------------------
__device__ __forceinline__ uint32_t f2tf32(float x)
{
    uint32_t r;
    asm("cvt.rna.tf32.f32 %0, %1;" : "=r"(r) : "f"(x));
    return r;
}
__device__ __forceinline__ float rna_f(float x) { return __uint_as_float(f2tf32(x)); }

__device__ __forceinline__ void mma_tf32(float* d, const uint32_t* a, const uint32_t* b)
{
    asm volatile(
        "mma.sync.aligned.m16n8k8.row.col.f32.tf32.tf32.f32 "
        "{%0,%1,%2,%3}, {%4,%5,%6,%7}, {%8,%9}, {%0,%1,%2,%3};\n"
        : "+f"(d[0]), "+f"(d[1]), "+f"(d[2]), "+f"(d[3])
        : "r"(a[0]), "r"(a[1]), "r"(a[2]), "r"(a[3]), "r"(b[0]), "r"(b[1]));
}

__device__ __forceinline__ void mbar_init(uint32_t a, uint32_t cnt)
{
    asm volatile("mbarrier.init.shared.b64 [%0], %1;" :: "r"(a), "r"(cnt) : "memory");
}
__device__ __forceinline__ void mbar_expect_tx(uint32_t a, uint32_t bytes)
{
    asm volatile("mbarrier.arrive.expect_tx.shared.b64 _, [%0], %1;"
                 :: "r"(a), "r"(bytes) : "memory");
}
__device__ __forceinline__ void mbar_wait(uint32_t a, uint32_t parity)
{
    asm volatile(
        "{\n\t.reg .pred P;\n\t"
        "LW%=:\n\t"
        "mbarrier.try_wait.parity.acquire.cta.shared::cta.b64 P, [%0], %1, 0x989680;\n\t"
        "@!P bra LW%=;\n\t"
        "}" :: "r"(a), "r"(parity) : "memory");
}
__device__ __forceinline__ void bulk_g2s(uint32_t dst, const float* src,
                                         uint32_t bytes, uint32_t mbar)
{
    asm volatile(
        "cp.async.bulk.shared::cluster.global.mbarrier::complete_tx::bytes "
        "[%0], [%1], %2, [%3];"
        :: "r"(dst), "l"(src), "r"(bytes), "r"(mbar) : "memory");
}

// ---------------------------------------------------------------------------
// TF32 GEMM: C[M,N] = A[M,K] @ B[K,N] (+bias)(gelu)(+res)(rna).
// A and B values pre-rounded to tf32 (in-HMMA truncation = identity).
// Grid (N/256, ceil(M/128)), 512 threads (16 warps, 4Mx4N, warp tile 32x64).
// N % 256 == 0, K % 32 == 0 required. M guarded.
// ---------------------------------------------------------------------------
__global__ __launch_bounds__(512, 1)
void tc_gemm(int M, int N, int K,
             const float* __restrict__ A, const float* __restrict__ B,
             float* __restrict__ C, const float* __restrict__ bias,
             const float* __restrict__ res, int do_gelu, int do_rna)
{
    extern __shared__ char smraw[];
    const uint32_t sb = (uint32_t)__cvta_generic_to_shared(smraw);
    const uint32_t sd = sb + CTRL;
    const uint32_t* smU = (const uint32_t*)(smraw + CTRL);

    const int tid  = threadIdx.x;
    const int wid  = tid >> 5;
    const int lane = tid & 31;
    const int gid  = lane >> 2;          // 0..7
    const int tig  = lane & 3;           // 0..3
    const int bx   = blockIdx.x;         // N tile (256)
    const int by   = blockIdx.y;         // M tile (128)

    const int warp_m = (wid & 3) * 32;   // 4 warps along M
    const int warp_n = (wid >> 2) * 64;  // 4 warps along N

    if (tid == 0) {
#pragma unroll
        for (int s = 0; s < STG; s++) mbar_init(sb + 8 * s, 1);
    }
    __syncthreads();

    const int nk = K / BKT;

    // stage fill: thread 0 posts expect_tx; threads 0..127 A rows, 128..159 B rows
    auto fill = [&](int slot, int kt) {
        const uint32_t base = sd + (uint32_t)slot * STAGE_B;
        const uint32_t mbar = sb + 8 * slot;
        if (tid == 0) mbar_expect_tx(mbar, KT_BYTES);
        if (tid < 128) {
            int grow = by * 128 + tid;
            const float* src = A + (size_t)(grow < M ? grow : 0) * K + kt * BKT;
            bulk_g2s(base + (uint32_t)tid * (A_STRIDE * 4), src, 128, mbar);
        } else if (tid < 128 + BKT) {
            int r = tid - 128;
            const float* src = B + (size_t)(kt * BKT + r) * N + bx * 256;
            bulk_g2s(base + A_SB + (uint32_t)r * (B_STRIDE * 4), src, 1024, mbar);
        }
    };

    float acc[2][8][4];
#pragma unroll
    for (int mm = 0; mm < 2; mm++)
#pragma unroll
        for (int nn = 0; nn < 8; nn++)
#pragma unroll
            for (int r = 0; r < 4; r++) acc[mm][nn][r] = 0.0f;

    // prologue
#pragma unroll
    for (int s = 0; s < STG; s++)
        if (s < nk) fill(s, s);

    for (int kt = 0; kt < nk; kt++) {
        const int slot = kt % STG;
        const uint32_t parity = ((uint32_t)(kt / STG)) & 1u;
        mbar_wait(sb + 8 * slot, parity);

        const uint32_t* As_ = smU + (size_t)slot * (STAGE_B / 4);
        const uint32_t* Bs_ = As_ + (A_SB / 4);

#pragma unroll
        for (int ks = 0; ks < 4; ks++) {
            const int kb = ks * 8;
            uint32_t a[2][4], b[8][2];
#pragma unroll
            for (int mm = 0; mm < 2; mm++) {
                int r0 = warp_m + mm * 16 + gid;
                a[mm][0] = As_[r0 * A_STRIDE + kb + tig];
                a[mm][1] = As_[(r0 + 8) * A_STRIDE + kb + tig];
                a[mm][2] = As_[r0 * A_STRIDE + kb + tig + 4];
                a[mm][3] = As_[(r0 + 8) * A_STRIDE + kb + tig + 4];
            }
#pragma unroll
            for (int nn = 0; nn < 8; nn++) {
                int c0 = warp_n + nn * 8 + gid;
                b[nn][0] = Bs_[(kb + tig) * B_STRIDE + c0];
                b[nn][1] = Bs_[(kb + tig + 4) * B_STRIDE + c0];
            }
#pragma unroll
            for (int mm = 0; mm < 2; mm++)
#pragma unroll
                for (int nn = 0; nn < 8; nn++)
                    mma_tf32(acc[mm][nn], a[mm], b[nn]);
        }

        __syncthreads();   // all warps done reading this slot
        if (kt + STG < nk) {
            asm volatile("fence.proxy.async.shared::cta;" ::: "memory");
            fill(slot, kt + STG);
        }
    }

    // ---- epilogue ----
#pragma unroll
    for (int mm = 0; mm < 2; mm++) {
#pragma unroll
        for (int half = 0; half < 2; half++) {
            int row = by * 128 + warp_m + mm * 16 + gid + half * 8;
            if (row >= M) continue;
#pragma unroll
            for (int nn = 0; nn < 8; nn++) {
                int col = bx * 256 + warp_n + nn * 8 + tig * 2;
                float v0 = acc[mm][nn][half * 2 + 0];
                float v1 = acc[mm][nn][half * 2 + 1];
                if (bias) { v0 += bias[col]; v1 += bias[col + 1]; }
                if (do_gelu) {
                    v0 = 0.5f * v0 * (1.0f + erff(v0 * 0.70710678118654752f));
                    v1 = 0.5f * v1 * (1.0f + erff(v1 * 0.70710678118654752f));
                }
                if (res) {
                    v0 += res[(size_t)row * N + col];
                    v1 += res[(size_t)row * N + col + 1];
                }
                if (do_rna) { v0 = rna_f(v0); v1 = rna_f(v1); }
                C[(size_t)row * N + col]     = v0;
                C[(size_t)row * N + col + 1] = v1;
            }
        }
    }
}

// ---------------------------------------------------------------------------
// Round two tensors to tf32 (RNA) in one launch. Sizes in float4 units.
// ---------------------------------------------------------------------------
__global__ void round2_kernel(const float* __restrict__ i1, float* __restrict__ o1,
                              int n1, const float* __restrict__ i2,
                              float* __restrict__ o2, int n2)
{
    int i = blockIdx.x * blockDim.x + threadIdx.x;
    if (i < n1) {
        float4 v = ((const float4*)i1)[i];
        v.x = rna_f(v.x); v.y = rna_f(v.y); v.z = rna_f(v.z); v.w = rna_f(v.w);
        ((float4*)o1)[i] = v;
    } else if (i - n1 < n2) {
        int j = i - n1;
        float4 v = ((const float4*)i2)[j];
        v.x = rna_f(v.x); v.y = rna_f(v.y); v.z = rna_f(v.z); v.w = rna_f(v.w);
        ((float4*)o2)[j] = v;
    }
}

// ---------------------------------------------------------------------------
// LayerNorm over width=1024, optional dual output, optional tf32 rounding.
// ---------------------------------------------------------------------------
__device__ __forceinline__ float2 block_reduce2(float a, float b)
{
    __shared__ float sa[8], sb_[8];
#pragma unroll
    for (int off = 16; off; off >>= 1) {
        a += __shfl_down_sync(0xFFFFFFFFu, a, off);
        b += __shfl_down_sync(0xFFFFFFFFu, b, off);
    }
    int w = threadIdx.x >> 5, l = threadIdx.x & 31;
    if (l == 0) { sa[w] = a; sb_[w] = b; }
    __syncthreads();
    if (w == 0) {
        a = (l < 8) ? sa[l] : 0.f;
        b = (l < 8) ? sb_[l] : 0.f;
#pragma unroll
        for (int off = 4; off; off >>= 1) {
            a += __shfl_down_sync(0xFFFFFFFFu, a, off);
            b += __shfl_down_sync(0xFFFFFFFFu, b, off);
        }
        if (l == 0) { sa[0] = a; sb_[0] = b; }
    }
    __syncthreads();
    return make_float2(sa[0], sb_[0]);
}

__global__ __launch_bounds__(256)
void ln_kernel(const float* __restrict__ in, float* __restrict__ out,
               float* __restrict__ out2,
               const float* __restrict__ g, const float* __restrict__ bta,
               int width, int rpb_in, int rpb_out, int out_off, int do_rna)
{
    int row = blockIdx.x;
    const float* x = in + (size_t)row * width;
    int bi = row / rpb_in, n = row % rpb_in;
    float* y = out + ((size_t)bi * rpb_out + out_off + n) * width;
    float* y2 = out2 ? out2 + (size_t)row * width : nullptr;

    float s = 0.f, s2 = 0.f;
    for (int i = threadIdx.x * 4; i < width; i += blockDim.x * 4) {
        float4 v = *(const float4*)(x + i);
        s  += v.x + v.y + v.z + v.w;
        s2 += v.x * v.x + v.y * v.y + v.z * v.z + v.w * v.w;
    }
    float2 r = block_reduce2(s, s2);
    float mean = r.x / (float)width;
    float var  = r.y / (float)width - mean * mean;
    float rstd = rsqrtf(var + 1e-5f);

    for (int i = threadIdx.x * 4; i < width; i += blockDim.x * 4) {
        float4 v = *(const float4*)(x + i);
        float4 gg = *(const float4*)(g + i);
        float4 bb = *(const float4*)(bta + i);
        float4 o;
        o.x = (v.x - mean) * rstd * gg.x + bb.x;
        o.y = (v.y - mean) * rstd * gg.y + bb.y;
        o.z = (v.z - mean) * rstd * gg.z + bb.z;
        o.w = (v.w - mean) * rstd * gg.w + bb.w;
        if (do_rna) {
            o.x = rna_f(o.x); o.y = rna_f(o.y); o.z = rna_f(o.z); o.w = rna_f(o.w);
        }
        *(float4*)(y + i) = o;
        if (y2) *(float4*)(y2 + i) = o;
    }
}

__global__ void bcast_kernel(const float* __restrict__ latents, float* __restrict__ lat)
{
    size_t i = (size_t)blockIdx.x * blockDim.x + threadIdx.x;
    size_t tot = (size_t)Bb * NQ * DIM;
    if (i < tot) lat[i] = latents[i % ((size_t)NQ * DIM)];
}

// ---------------------------------------------------------------------------
// Attention: per block (b, h, q-tile of 16 rows). fp32; output RNA-rounded.
// ---------------------------------------------------------------------------
__global__ __launch_bounds__(256)
void attn_kernel(const float* __restrict__ q,
                 const float* __restrict__ kv,
                 float* __restrict__ o)
{
    __shared__ float qs[16][DH];
    __shared__ float sc[16][NK];

    int blk = blockIdx.x;
    int qt = blk & 3;
    int h  = (blk >> 2) & 15;
    int b  = blk >> 6;

    const float* qbase = q + ((size_t)b * NQ + qt * 16) * DIM + h * DH;
    for (int i = threadIdx.x; i < 16 * DH; i += 256) {
        int r = i >> 6, c = i & 63;
        qs[r][c] = qbase[(size_t)r * DIM + c];
    }
    __syncthreads();

    const float* kbase = kv + (size_t)b * NK * (2 * DIM) + h * DH;
    const float* vbase = kbase + DIM;

    for (int idx = threadIdx.x; idx < 16 * NK; idx += 256) {
        int r = idx / NK, kk = idx % NK;
        const float* krow = kbase + (size_t)kk * (2 * DIM);
        float acc = 0.f;
#pragma unroll
        for (int d = 0; d < DH; d += 4) {
            float4 k4 = *(const float4*)(krow + d);
            acc += qs[r][d] * k4.x + qs[r][d + 1] * k4.y
                 + qs[r][d + 2] * k4.z + qs[r][d + 3] * k4.w;
        }
        sc[r][kk] = acc * 0.125f;
    }
    __syncthreads();

    int warp = threadIdx.x >> 5, lane = threadIdx.x & 31;
    for (int r = warp * 2; r < warp * 2 + 2; r++) {
        float mx = -1e30f;
        for (int k = lane; k < NK; k += 32) mx = fmaxf(mx, sc[r][k]);
#pragma unroll
        for (int off = 16; off; off >>= 1)
            mx = fmaxf(mx, __shfl_xor_sync(0xFFFFFFFFu, mx, off));
        float sum = 0.f;
        for (int k = lane; k < NK; k += 32) {
            float e = __expf(sc[r][k] - mx);
            sc[r][k] = e;
            sum += e;
        }
#pragma unroll
        for (int off = 16; off; off >>= 1)
            sum += __shfl_xor_sync(0xFFFFFFFFu, sum, off);
        float inv = 1.0f / sum;
        for (int k = lane; k < NK; k += 32) sc[r][k] *= inv;
    }
    __syncthreads();

    int d = threadIdx.x & 63;
    int r0 = threadIdx.x >> 6;
    float acc[4] = {0.f, 0.f, 0.f, 0.f};
    for (int k = 0; k < NK; k++) {
        float vv = vbase[(size_t)k * (2 * DIM) + d];
#pragma unroll
        for (int j = 0; j < 4; j++)
            acc[j] = fmaf(sc[r0 + 4 * j][k], vv, acc[j]);
    }
    float* obase = o + ((size_t)b * NQ + qt * 16) * DIM + h * DH;
#pragma unroll
    for (int j = 0; j < 4; j++)
        obase[(size_t)(r0 + 4 * j) * DIM + d] = rna_f(acc[j]);
}

// ---------------------------------------------------------------------------
static inline void gemm(const float* A, const float* B, float* C,
                        int M, int N, int K,
                        const float* bias, const float* res, int do_gelu, int do_rna)
{
    dim3 grid(N / 256, (M + 127) / 128);
    tc_gemm<<<grid, 512, GSMEM>>>(M, N, K, A, B, C, bias, res, do_gelu, do_rna);
}

extern "C" void kernel_launch(void* const* d_in, const int* in_sizes, int n_in,
                              void* d_out, int out_size)
{
    const float* x          = (const float*)d_in[0];
    const float* latents    = (const float*)d_in[1];
    const float* proj_in_w  = (const float*)d_in[2];
    const float* proj_in_b  = (const float*)d_in[3];
    const float* ln1_g      = (const float*)d_in[4];
    const float* ln1_b      = (const float*)d_in[5];
    const float* ln2_g      = (const float*)d_in[6];
    const float* ln2_b      = (const float*)d_in[7];
    const float* Wq         = (const float*)d_in[8];
    const float* Wkv        = (const float*)d_in[9];
    const float* Wo         = (const float*)d_in[10];
    const float* ff_ln_g    = (const float*)d_in[11];
    const float* ff_ln_b    = (const float*)d_in[12];
    const float* ff_w1      = (const float*)d_in[13];
    const float* ff_w2      = (const float*)d_in[14];
    const float* proj_out_w = (const float*)d_in[15];
    const float* proj_out_b = (const float*)d_in[16];
    const float* norm_out_g = (const float*)d_in[17];
    const float* norm_out_b = (const float*)d_in[18];
    float* out = (float*)d_out;

    cudaFuncSetAttribute(tc_gemm, cudaFuncAttributeMaxDynamicSharedMemorySize, GSMEM);

    float *xf, *cat, *lat, *lnlat, *qb, *kvb, *ob, *hb, *tmp, *xr, *wt;
    cudaGetSymbolAddress((void**)&xf,    g_xf);
    cudaGetSymbolAddress((void**)&cat,   g_cat);
    cudaGetSymbolAddress((void**)&lat,   g_lat);
    cudaGetSymbolAddress((void**)&lnlat, g_lnlat);
    cudaGetSymbolAddress((void**)&qb,    g_q);
    cudaGetSymbolAddress((void**)&kvb,   g_kv);
    cudaGetSymbolAddress((void**)&ob,    g_o);
    cudaGetSymbolAddress((void**)&hb,    g_h);
    cudaGetSymbolAddress((void**)&tmp,   g_tmp);
    cudaGetSymbolAddress((void**)&xr,    g_xr);
    cudaGetSymbolAddress((void**)&wt,    g_wt);

    const int Mx = Bb * N1;   // 8224
    const int Ml = Bb * NQ;   // 2048
    const int Mc = Bb * NK;   // 10272

    // ---- prep (launches #0..#4): RNA-round all weights + x; bcast latents --
    {
        // #0: Wq + Wo (2M + 2M float4)
        int n1 = 8 * DIM * DIM / 4, n2 = 8 * DIM * DIM / 4;
        round2_kernel<<<(n1 + n2 + 255) / 256, 256>>>(
            Wq, wt + OFF_WQ, n1, Wo, wt + OFF_WO, n2);
        // #1: Wkv + W1
        n1 = 8 * DIM * 2 * DIM / 4; n2 = 8 * DIM * FFI / 4;
        round2_kernel<<<(n1 + n2 + 255) / 256, 256>>>(
            Wkv, wt + OFF_WKV, n1, ff_w1, wt + OFF_W1, n2);
        // #2: W2 + proj_out_w
        n1 = 8 * FFI * DIM / 4; n2 = DIM * DIM / 4;
        round2_kernel<<<(n1 + n2 + 255) / 256, 256>>>(
            ff_w2, wt + OFF_W2, n1, proj_out_w, wt + OFF_POUT, n2);
        // #3: proj_in_w + x
        n1 = EMB * DIM / 4; n2 = Bb * N1 * EMB / 4;
        round2_kernel<<<(n1 + n2 + 255) / 256, 256>>>(
            proj_in_w, wt + OFF_PIN, n1, x, xr, n2);
        // #4: broadcast latents
        size_t tot = (size_t)Bb * NQ * DIM;
        bcast_kernel<<<(int)((tot + 255) / 256), 256>>>(latents, lat);
    }

    // #5: proj_in GEMM (profiled by ncu -s 5 -c 1)
    gemm(xr, wt + OFF_PIN, xf, Mx, DIM, EMB, proj_in_b, nullptr, 0, 0);

    for (int i = 0; i < DEPTH; i++) {
        const float* wq  = wt + OFF_WQ  + (size_t)i * DIM * DIM;
        const float* wkv = wt + OFF_WKV + (size_t)i * DIM * 2 * DIM;
        const float* wo  = wt + OFF_WO  + (size_t)i * DIM * DIM;
        const float* w1  = wt + OFF_W1  + (size_t)i * DIM * FFI;
        const float* w2  = wt + OFF_W2  + (size_t)i * FFI * DIM;

        // ln(xf) -> cat rows [0,257)  (rounded: feeds kv gemm)
        ln_kernel<<<Mx, 256>>>(xf, cat, nullptr,
                               ln1_g + (size_t)i * DIM, ln1_b + (size_t)i * DIM,
                               DIM, N1, NK, 0, 1);
        // ln(lat) -> cat rows [257,321) AND lnlat (rounded: feeds kv + q)
        ln_kernel<<<Ml, 256>>>(lat, cat, lnlat,
                               ln2_g + (size_t)i * DIM, ln2_b + (size_t)i * DIM,
                               DIM, NQ, NK, N1, 1);

        gemm(lnlat, wq, qb, Ml, DIM, DIM, nullptr, nullptr, 0, 0);       // q
        gemm(cat, wkv, kvb, Mc, 2 * DIM, DIM, nullptr, nullptr, 0, 0);   // kv

        attn_kernel<<<Bb * HEADS * 4, 256>>>(qb, kvb, ob);               // ob (rna)

        gemm(ob, wo, lat, Ml, DIM, DIM, nullptr, lat, 0, 0);             // lat += o@Wo

        ln_kernel<<<Ml, 256>>>(lat, lnlat, nullptr,
                               ff_ln_g + (size_t)i * DIM, ff_ln_b + (size_t)i * DIM,
                               DIM, NQ, NQ, 0, 1);
        gemm(lnlat, w1, hb, Ml, FFI, DIM, nullptr, nullptr, 1, 1);       // gelu+rna
        gemm(hb, w2, lat, Ml, DIM, FFI, nullptr, lat, 0, 0);             // lat += h@W2
    }

    // round lat for proj_out A-side, then proj_out + final LN
    {
        int n4 = Bb * NQ * DIM / 4;
        round2_kernel<<<(n4 + 255) / 256, 256>>>(lat, lnlat, n4, nullptr, nullptr, 0);
    }
    gemm(lnlat, wt + OFF_POUT, tmp, Ml, DIM, DIM, proj_out_b, nullptr, 0, 0);
    ln_kernel<<<Ml, 256>>>(tmp, out, nullptr, norm_out_g, norm_out_b, DIM, NQ, NQ, 0, 0);
}